// round 14
// baseline (speedup 1.0000x reference)
#include <cuda_runtime.h>
#include <cstdint>

#define BATCH   64
#define D_IN    512
#define D_OUT   512
#define GRID_N  100
#define LN_EPS   1e-5f
#define GRID_EPS 1e-6f

#define ICH     32                  // i's per gather CTA
#define NICH    (D_IN / ICH)        // 16 chunks
#define OBL     8                   // o's per gather CTA
#define NOBL    (D_OUT / OBL)       // 64 o-blocks
#define NSTAGE  4                   // pipeline depth (smem buffers)

#define ISTRIDE  (D_OUT * GRID_N * 4)   // 204800 floats per i
#define OSTRIDE  (GRID_N * 4)           // 400 floats per o
#define TILE_FLOATS (OBL * OSTRIDE)     // 3200 floats = 12.8 KB, contiguous
#define TILE_U4     (TILE_FLOATS / 4)   // 800 16B chunks

// ---- scratch (__device__ globals; no allocations allowed) ----
__device__ float g_scaled[D_IN * BATCH];             // transposed [i][b]
__device__ float g_partial[NICH * BATCH * D_OUT];    // 2.1 MB

// ---- cp.async / griddep helpers ----
__device__ __forceinline__ void cp16(void* sdst, const void* gsrc)
{
    unsigned int a = (unsigned int)__cvta_generic_to_shared(sdst);
    asm volatile("cp.async.cg.shared.global [%0], [%1], 16;"
                 :: "r"(a), "l"(gsrc));
}
#define CP_COMMIT()   asm volatile("cp.async.commit_group;" ::: "memory")
#define CP_WAIT2()    asm volatile("cp.async.wait_group 2;" ::: "memory")
#define GDC_TRIGGER() asm volatile("griddepcontrol.launch_dependents;" ::: "memory")
#define GDC_WAIT()    asm volatile("griddepcontrol.wait;" ::: "memory")

// ---------------------------------------------------------------------------
// Kernel 1: LayerNorm -> clamped scaled coordinate. Triggers dependent launch
// immediately so the gather grid's cp.async prefetches overlap this kernel.
// ---------------------------------------------------------------------------
__global__ __launch_bounds__(128) void prep_kernel(
    const float* __restrict__ x,
    const float* __restrict__ ln_w,
    const float* __restrict__ ln_b)
{
    GDC_TRIGGER();   // let gather CTAs launch + prefetch now

    const int b = blockIdx.x;
    const int t = threadIdx.x;

    __shared__ float red1[4], red2[4];

    const float4 v = reinterpret_cast<const float4*>(x + b * D_IN)[t];

    float s1 = v.x + v.y + v.z + v.w;
    float s2 = v.x * v.x + v.y * v.y + v.z * v.z + v.w * v.w;
    #pragma unroll
    for (int off = 16; off > 0; off >>= 1) {
        s1 += __shfl_xor_sync(0xffffffffu, s1, off);
        s2 += __shfl_xor_sync(0xffffffffu, s2, off);
    }
    if ((t & 31) == 0) { red1[t >> 5] = s1; red2[t >> 5] = s2; }
    __syncthreads();
    if (t < 32) {
        float r1 = (t < 4) ? red1[t] : 0.0f;
        float r2 = (t < 4) ? red2[t] : 0.0f;
        #pragma unroll
        for (int off = 2; off > 0; off >>= 1) {
            r1 += __shfl_xor_sync(0xffffffffu, r1, off);
            r2 += __shfl_xor_sync(0xffffffffu, r2, off);
        }
        if (t == 0) { red1[0] = r1; red2[0] = r2; }
    }
    __syncthreads();

    const float mean = red1[0] * (1.0f / D_IN);
    const float var  = red2[0] * (1.0f / D_IN) - mean * mean;
    const float rstd = rsqrtf(var + LN_EPS);

    const float4 lw = reinterpret_cast<const float4*>(ln_w)[t];
    const float4 lb = reinterpret_cast<const float4*>(ln_b)[t];

    const float vv[4] = { v.x, v.y, v.z, v.w };
    const float ww[4] = { lw.x, lw.y, lw.z, lw.w };
    const float bb[4] = { lb.x, lb.y, lb.z, lb.w };

    #pragma unroll
    for (int j = 0; j < 4; j++) {
        const int i = t * 4 + j;
        float xn = (vv[j] - mean) * rstd * ww[j] + bb[j];
        xn = fminf(fmaxf(xn, -1.0f + GRID_EPS), 1.0f - GRID_EPS);
        xn = (xn + 1.0f) * 0.5f;
        g_scaled[i * BATCH + b] = xn * (float)GRID_N;   // in [0, 100)
    }
}

// ---------------------------------------------------------------------------
// Kernel 2: dense-streaming evaluation, 4-stage cp.async pipeline, 3 tiles
// prefetched in the PDL pre-sync region (overlapping prep), ONE sync per tile.
// grid = (NOBL=64, NICH=16), block = (64 b, 8 o) = 512 thr.
// ---------------------------------------------------------------------------
__global__ __launch_bounds__(512) void gather_kernel(
    const float* __restrict__ poly,
    const float* __restrict__ M)
{
    const int b   = threadIdx.x;                 // 0..63
    const int ol  = threadIdx.y;                 // 0..7
    const int ch  = blockIdx.y;
    const int i0  = ch * ICH;
    const int tid = ol * 64 + b;

    __shared__ float buf[NSTAGE][TILE_FLOATS];   // 51.2 KB
    __shared__ float ssc[ICH * BATCH];           // 8 KB
    __shared__ float sM[16];

    const float* tb = poly + (size_t)i0 * ISTRIDE
                           + (size_t)blockIdx.x * TILE_FLOATS;

    // ---- PDL pre-sync region: prefetch tiles 0,1,2 (independent of prep) ----
    if (tid < 16) sM[tid] = M[tid];
    #pragma unroll
    for (int p = 0; p < 3; p++) {
        const float* s = tb + (size_t)p * ISTRIDE;
        if (tid < TILE_U4)        cp16(&buf[p][tid * 4],         s + tid * 4);
        if (tid + 512 < TILE_U4)  cp16(&buf[p][(tid + 512) * 4], s + (tid + 512) * 4);
        CP_COMMIT();
    }

    // ---- wait for prep's g_scaled ----
    GDC_WAIT();

    for (int e = tid; e < ICH * BATCH; e += 512)
        ssc[e] = g_scaled[i0 * BATCH + e];
    // (no explicit sync: the loop's first __syncthreads covers ssc visibility)

    float acc = 0.0f;

    for (int ii = 0; ii < ICH; ii++) {
        CP_WAIT2();          // <=2 groups pending -> tile ii landed
        __syncthreads();     // tile ii visible; everyone done with iter ii-1

        const float sc = ssc[ii * BATCH + b];
        int gi = (int)sc;                       // sc >= 0 -> trunc == floor
        gi = min(gi, GRID_N - 1);
        const float t  = sc - (float)gi;
        const float t2 = t * t;
        const float t3 = t2 * t;

        float4 w;
        w.x = sM[0] + t * sM[4] + t2 * sM[8]  + t3 * sM[12];
        w.y = sM[1] + t * sM[5] + t2 * sM[9]  + t3 * sM[13];
        w.z = sM[2] + t * sM[6] + t2 * sM[10] + t3 * sM[14];
        w.w = sM[3] + t * sM[7] + t2 * sM[11] + t3 * sM[15];

        const float4 pv = *reinterpret_cast<const float4*>(
            &buf[ii % NSTAGE][ol * OSTRIDE + gi * 4]);
        acc += w.x * pv.x + w.y * pv.y + w.z * pv.z + w.w * pv.w;

        // prefetch tile ii+3 into buf[(ii+3)%4] (= buffer read in iter ii-1;
        // safe: the sync above proves all threads finished iter ii-1)
        if (ii + 3 < ICH) {
            const float* s = tb + (size_t)(ii + 3) * ISTRIDE;
            float* d = buf[(ii + 3) % NSTAGE];
            if (tid < TILE_U4)        cp16(&d[tid * 4],         s + tid * 4);
            if (tid + 512 < TILE_U4)  cp16(&d[(tid + 512) * 4], s + (tid + 512) * 4);
        }
        CP_COMMIT();         // always commit -> group counting stays aligned
    }

    const int o = blockIdx.x * OBL + ol;
    g_partial[((size_t)ch * BATCH + b) * D_OUT + o] = acc;
}

// ---------------------------------------------------------------------------
// Kernel 3: reduce partials over 16 chunks (PDL-overlapped).
// ---------------------------------------------------------------------------
__global__ __launch_bounds__(128) void reduce_kernel(float* __restrict__ out)
{
    const int idx4 = blockIdx.x * 128 + threadIdx.x;     // 0..8191
    const float4* p = reinterpret_cast<const float4*>(g_partial) + idx4;

    GDC_WAIT();

    float4 v[NICH];
    #pragma unroll
    for (int c = 0; c < NICH; c++)
        v[c] = p[(size_t)c * (BATCH * D_OUT / 4)];

    float4 acc = make_float4(0.f, 0.f, 0.f, 0.f);
    #pragma unroll
    for (int c = 0; c < NICH; c++) {
        acc.x += v[c].x; acc.y += v[c].y;
        acc.z += v[c].z; acc.w += v[c].w;
    }

    reinterpret_cast<float4*>(out)[idx4] = acc;
}

// ---------------------------------------------------------------------------
extern "C" void kernel_launch(void* const* d_in, const int* in_sizes, int n_in,
                              void* d_out, int out_size)
{
    const float* x    = (const float*)d_in[0];   // (64, 512)
    const float* poly = (const float*)d_in[1];   // (512, 512, 100, 4)
    const float* ln_w = (const float*)d_in[2];   // (512,)
    const float* ln_b = (const float*)d_in[3];   // (512,)
    const float* M    = (const float*)d_in[4];   // (4, 4)
    float* out = (float*)d_out;                  // (64, 512) fp32

    prep_kernel<<<BATCH, 128>>>(x, ln_w, ln_b);

    {   // gather: PDL — 3-tile prefetch overlaps prep (early trigger in prep)
        cudaLaunchConfig_t cfg = {};
        cfg.gridDim  = dim3(NOBL, NICH);
        cfg.blockDim = dim3(64, OBL);
        cudaLaunchAttribute attr[1];
        attr[0].id = cudaLaunchAttributeProgrammaticStreamSerialization;
        attr[0].val.programmaticStreamSerializationAllowed = 1;
        cfg.attrs = attr;
        cfg.numAttrs = 1;
        cudaLaunchKernelEx(&cfg, gather_kernel, poly, M);
    }

    {   // reduce: PDL — overlaps gather's drain
        cudaLaunchConfig_t cfg = {};
        cfg.gridDim  = dim3((BATCH * D_OUT / 4) / 128);
        cfg.blockDim = dim3(128);
        cudaLaunchAttribute attr[1];
        attr[0].id = cudaLaunchAttributeProgrammaticStreamSerialization;
        attr[0].val.programmaticStreamSerializationAllowed = 1;
        cfg.attrs = attr;
        cfg.numAttrs = 1;
        cudaLaunchKernelEx(&cfg, reduce_kernel, out);
    }
}

// round 15
// speedup vs baseline: 1.0735x; 1.0735x over previous
#include <cuda_runtime.h>
#include <cstdint>

#define BATCH   64
#define D_IN    512
#define D_OUT   512
#define GRID_N  100
#define LN_EPS   1e-5f
#define GRID_EPS 1e-6f

#define ICH     64                  // i's per gather CTA
#define NICH    (D_IN / ICH)        // 8 chunks
#define OBL     8                   // o's per gather CTA
#define NOBL    (D_OUT / OBL)       // 64 o-blocks -> grid 512 = ONE wave
#define NSTAGE  3                   // pipeline depth (proven best)

#define ISTRIDE  (D_OUT * GRID_N * 4)   // 204800 floats per i
#define OSTRIDE  (GRID_N * 4)           // 400 floats per o
#define TILE_FLOATS (OBL * OSTRIDE)     // 3200 floats = 12.8 KB, contiguous
#define TILE_U4     (TILE_FLOATS / 4)   // 800 16B chunks
#define TILE_LINES  (TILE_FLOATS / 32)  // 100 128B lines

// dynamic smem layout (floats): buf[NSTAGE][TILE_FLOATS] | ssc[ICH*BATCH] | sM[16]
#define SM_BUF    0
#define SM_SSC    (NSTAGE * TILE_FLOATS)            // 9600
#define SM_M      (SM_SSC + ICH * BATCH)            // 13696
#define SM_FLOATS (SM_M + 16)                       // 13712 -> 54848 B
#define SM_BYTES  (SM_FLOATS * 4)

// ---- scratch (__device__ globals; no allocations allowed) ----
__device__ float g_scaled[D_IN * BATCH];             // transposed [i][b]
__device__ float g_partial[NICH * BATCH * D_OUT];    // 1.05 MB

// ---- cp.async / griddep helpers ----
__device__ __forceinline__ void cp16(void* sdst, const void* gsrc)
{
    unsigned int a = (unsigned int)__cvta_generic_to_shared(sdst);
    asm volatile("cp.async.cg.shared.global [%0], [%1], 16;"
                 :: "r"(a), "l"(gsrc));
}
__device__ __forceinline__ void l2_prefetch(const void* g)
{
    asm volatile("prefetch.global.L2 [%0];" :: "l"(g));
}
#define CP_COMMIT()   asm volatile("cp.async.commit_group;" ::: "memory")
#define CP_WAIT1()    asm volatile("cp.async.wait_group 1;" ::: "memory")
#define GDC_TRIGGER() asm volatile("griddepcontrol.launch_dependents;" ::: "memory")
#define GDC_WAIT()    asm volatile("griddepcontrol.wait;" ::: "memory")

// ---------------------------------------------------------------------------
// Kernel 1: LayerNorm -> clamped scaled coordinate. Early PDL trigger.
// ---------------------------------------------------------------------------
__global__ __launch_bounds__(128) void prep_kernel(
    const float* __restrict__ x,
    const float* __restrict__ ln_w,
    const float* __restrict__ ln_b)
{
    GDC_TRIGGER();   // let gather CTAs launch + prefetch now

    const int b = blockIdx.x;
    const int t = threadIdx.x;

    __shared__ float red1[4], red2[4];

    const float4 v = reinterpret_cast<const float4*>(x + b * D_IN)[t];

    float s1 = v.x + v.y + v.z + v.w;
    float s2 = v.x * v.x + v.y * v.y + v.z * v.z + v.w * v.w;
    #pragma unroll
    for (int off = 16; off > 0; off >>= 1) {
        s1 += __shfl_xor_sync(0xffffffffu, s1, off);
        s2 += __shfl_xor_sync(0xffffffffu, s2, off);
    }
    if ((t & 31) == 0) { red1[t >> 5] = s1; red2[t >> 5] = s2; }
    __syncthreads();
    if (t < 32) {
        float r1 = (t < 4) ? red1[t] : 0.0f;
        float r2 = (t < 4) ? red2[t] : 0.0f;
        #pragma unroll
        for (int off = 2; off > 0; off >>= 1) {
            r1 += __shfl_xor_sync(0xffffffffu, r1, off);
            r2 += __shfl_xor_sync(0xffffffffu, r2, off);
        }
        if (t == 0) { red1[0] = r1; red2[0] = r2; }
    }
    __syncthreads();

    const float mean = red1[0] * (1.0f / D_IN);
    const float var  = red2[0] * (1.0f / D_IN) - mean * mean;
    const float rstd = rsqrtf(var + LN_EPS);

    const float4 lw = reinterpret_cast<const float4*>(ln_w)[t];
    const float4 lb = reinterpret_cast<const float4*>(ln_b)[t];

    const float vv[4] = { v.x, v.y, v.z, v.w };
    const float ww[4] = { lw.x, lw.y, lw.z, lw.w };
    const float bb[4] = { lb.x, lb.y, lb.z, lb.w };

    #pragma unroll
    for (int j = 0; j < 4; j++) {
        const int i = t * 4 + j;
        float xn = (vv[j] - mean) * rstd * ww[j] + bb[j];
        xn = fminf(fmaxf(xn, -1.0f + GRID_EPS), 1.0f - GRID_EPS);
        xn = (xn + 1.0f) * 0.5f;
        g_scaled[i * BATCH + b] = xn * (float)GRID_N;   // in [0, 100)
    }
}

// ---------------------------------------------------------------------------
// Kernel 2: dense-streaming evaluation. ONE wave (512 CTAs, 4/SM), 3-stage
// cp.async pipeline, pre-sync smem prefetch of tiles 0,1 + L2 warm-up of
// tiles 2..7, one __syncthreads per tile.
// grid = (NOBL=64, NICH=8), block = (64 b, 8 o) = 512 thr.
// ---------------------------------------------------------------------------
__global__ __launch_bounds__(512) void gather_kernel(
    const float* __restrict__ poly,
    const float* __restrict__ M)
{
    const int b   = threadIdx.x;                 // 0..63
    const int ol  = threadIdx.y;                 // 0..7
    const int ch  = blockIdx.y;
    const int i0  = ch * ICH;
    const int tid = ol * 64 + b;

    extern __shared__ float smem[];
    float* buf = smem + SM_BUF;                  // [NSTAGE][TILE_FLOATS]
    float* ssc = smem + SM_SSC;                  // [ICH*BATCH]
    float* sM  = smem + SM_M;                    // [16]

    const float* tb = poly + (size_t)i0 * ISTRIDE
                           + (size_t)blockIdx.x * TILE_FLOATS;

    // ---- PDL pre-sync region (independent of prep) ----
    if (tid < 16) sM[tid] = M[tid];

    #pragma unroll
    for (int p = 0; p < 2; p++) {                // smem prefetch tiles 0,1
        const float* s = tb + (size_t)p * ISTRIDE;
        float* d = buf + p * TILE_FLOATS;
        if (tid < TILE_U4)        cp16(&d[tid * 4],         s + tid * 4);
        if (tid + 512 < TILE_U4)  cp16(&d[(tid + 512) * 4], s + (tid + 512) * 4);
        CP_COMMIT();
    }
    {   // L2 warm-up: tiles 2..7 (600 lines; DRAM is idle while prep runs)
        const int nlines = 6 * TILE_LINES;       // 600
        if (tid < nlines)
            l2_prefetch(tb + 2 * ISTRIDE + (size_t)tid * 32);
        if (tid + 512 < nlines)
            l2_prefetch(tb + 2 * ISTRIDE + (size_t)(tid + 512) * 32);
    }

    // ---- wait for prep's g_scaled ----
    GDC_WAIT();

    #pragma unroll
    for (int e = tid; e < ICH * BATCH; e += 512)
        ssc[e] = g_scaled[i0 * BATCH + e];
    // (first __syncthreads in the loop covers ssc visibility)

    float acc = 0.0f;

    for (int ii = 0; ii < ICH; ii++) {
        CP_WAIT1();          // <=1 group pending -> tile ii landed
        __syncthreads();     // tile ii visible; everyone done with iter ii-1

        const float sc = ssc[ii * BATCH + b];
        int gi = (int)sc;                       // sc >= 0 -> trunc == floor
        gi = min(gi, GRID_N - 1);
        const float t  = sc - (float)gi;
        const float t2 = t * t;
        const float t3 = t2 * t;

        float4 w;
        w.x = sM[0] + t * sM[4] + t2 * sM[8]  + t3 * sM[12];
        w.y = sM[1] + t * sM[5] + t2 * sM[9]  + t3 * sM[13];
        w.z = sM[2] + t * sM[6] + t2 * sM[10] + t3 * sM[14];
        w.w = sM[3] + t * sM[7] + t2 * sM[11] + t3 * sM[15];

        const float4 pv = *reinterpret_cast<const float4*>(
            &buf[(ii % NSTAGE) * TILE_FLOATS + ol * OSTRIDE + gi * 4]);
        acc += w.x * pv.x + w.y * pv.y + w.z * pv.z + w.w * pv.w;

        // prefetch tile ii+2 into buf[(ii+2)%3] (read in iter ii-1; safe
        // past the sync above)
        if (ii + 2 < ICH) {
            const float* s = tb + (size_t)(ii + 2) * ISTRIDE;
            float* d = buf + ((ii + 2) % NSTAGE) * TILE_FLOATS;
            if (tid < TILE_U4)        cp16(&d[tid * 4],         s + tid * 4);
            if (tid + 512 < TILE_U4)  cp16(&d[(tid + 512) * 4], s + (tid + 512) * 4);
        }
        CP_COMMIT();         // always commit -> group counting stays aligned
    }

    const int o = blockIdx.x * OBL + ol;
    g_partial[((size_t)ch * BATCH + b) * D_OUT + o] = acc;
}

// ---------------------------------------------------------------------------
// Kernel 3: reduce partials over 8 chunks (PDL-overlapped).
// ---------------------------------------------------------------------------
__global__ __launch_bounds__(128) void reduce_kernel(float* __restrict__ out)
{
    const int idx4 = blockIdx.x * 128 + threadIdx.x;     // 0..8191
    const float4* p = reinterpret_cast<const float4*>(g_partial) + idx4;

    GDC_WAIT();

    float4 v[NICH];
    #pragma unroll
    for (int c = 0; c < NICH; c++)
        v[c] = p[(size_t)c * (BATCH * D_OUT / 4)];

    float4 acc = make_float4(0.f, 0.f, 0.f, 0.f);
    #pragma unroll
    for (int c = 0; c < NICH; c++) {
        acc.x += v[c].x; acc.y += v[c].y;
        acc.z += v[c].z; acc.w += v[c].w;
    }

    reinterpret_cast<float4*>(out)[idx4] = acc;
}

// ---------------------------------------------------------------------------
extern "C" void kernel_launch(void* const* d_in, const int* in_sizes, int n_in,
                              void* d_out, int out_size)
{
    const float* x    = (const float*)d_in[0];   // (64, 512)
    const float* poly = (const float*)d_in[1];   // (512, 512, 100, 4)
    const float* ln_w = (const float*)d_in[2];   // (512,)
    const float* ln_b = (const float*)d_in[3];   // (512,)
    const float* M    = (const float*)d_in[4];   // (4, 4)
    float* out = (float*)d_out;                  // (64, 512) fp32

    static bool attr_done = false;
    if (!attr_done) {
        cudaFuncSetAttribute(gather_kernel,
                             cudaFuncAttributeMaxDynamicSharedMemorySize,
                             SM_BYTES);
        attr_done = true;
    }

    prep_kernel<<<BATCH, 128>>>(x, ln_w, ln_b);

    {   // gather: PDL — prefetch + L2 warm-up overlap prep
        cudaLaunchConfig_t cfg = {};
        cfg.gridDim  = dim3(NOBL, NICH);
        cfg.blockDim = dim3(64, OBL);
        cfg.dynamicSmemBytes = SM_BYTES;
        cudaLaunchAttribute attr[1];
        attr[0].id = cudaLaunchAttributeProgrammaticStreamSerialization;
        attr[0].val.programmaticStreamSerializationAllowed = 1;
        cfg.attrs = attr;
        cfg.numAttrs = 1;
        cudaLaunchKernelEx(&cfg, gather_kernel, poly, M);
    }

    {   // reduce: PDL — overlaps gather's drain
        cudaLaunchConfig_t cfg = {};
        cfg.gridDim  = dim3((BATCH * D_OUT / 4) / 128);
        cfg.blockDim = dim3(128);
        cudaLaunchAttribute attr[1];
        attr[0].id = cudaLaunchAttributeProgrammaticStreamSerialization;
        attr[0].val.programmaticStreamSerializationAllowed = 1;
        cfg.attrs = attr;
        cfg.numAttrs = 1;
        cudaLaunchKernelEx(&cfg, reduce_kernel, out);
    }
}